// round 12
// baseline (speedup 1.0000x reference)
#include <cuda_runtime.h>
#include <cuda_fp16.h>
#include <cstdint>

// Problem dims (fixed by the dataset)
#define O_DIM   4096
#define I_DIM   2048
#define K_ACT   2048
#define N_TOK   4096
#define M_DENSE 8192

// Scratch (device globals; allocation-free rule): fp16 operands
__device__ __half g_Wh[(size_t)O_DIM * K_ACT];   // gathered weight, fp16
__device__ __half g_Bh[(size_t)N_TOK * K_ACT];   // activations, fp16

// ===========================================================================
// Fused prep kernel: two independent jobs, branch on blockIdx.x.
//   [0, 8192)      : gather weight -> Wh (4 elems/thread, latency-bound)
//   [8192, 12288)  : fp16-convert activations (BW-bound)
// (inactive-row zeroing moved into the GEMM kernel's wave tail)
// ===========================================================================
#define PREP_G1 8192
#define PREP_G2 4096
#define PREP_GRID (PREP_G1 + PREP_G2)

__global__ __launch_bounds__(256)
void prep_kernel(const float* __restrict__ weight,
                 const int*   __restrict__ idx,
                 const int*   __restrict__ metadata,
                 const float4* __restrict__ input) {
    int blk = blockIdx.x;
    if (blk < PREP_G1) {
        // ---- gather compressed weight -> Wh[o][j], fp16, 4 elems/thread ----
        int t  = blk * 256 + threadIdx.x;
        int o  = t >> 9;
        int j0 = (t & 511) << 2;
        const int4 kd4 = *reinterpret_cast<const int4*>(idx + j0);
        const int* md_row = metadata + (size_t)o * I_DIM;
        const float* w_row = weight + (size_t)o * I_DIM;
        int kd[4] = {kd4.x, kd4.y, kd4.z, kd4.w};
        float v[4];
#pragma unroll
        for (int e = 0; e < 4; e++) {
            int g = kd[e] >> 2;
            int p = kd[e] & 3;
            int2 md = *reinterpret_cast<const int2*>(md_row + 2 * g);
            float r = 0.0f;
            if (md.x == p)      r = __ldg(w_row + 2 * g);
            else if (md.y == p) r = __ldg(w_row + 2 * g + 1);
            v[e] = r;
        }
        __half2 h01 = __floats2half2_rn(v[0], v[1]);
        __half2 h23 = __floats2half2_rn(v[2], v[3]);
        uint2 pack;
        pack.x = *reinterpret_cast<uint32_t*>(&h01);
        pack.y = *reinterpret_cast<uint32_t*>(&h23);
        *reinterpret_cast<uint2*>(g_Wh + (size_t)o * K_ACT + j0) = pack;
    } else {
        // ---- fp16-convert activations: 8 floats/thread ----
        int t = (blk - PREP_G1) * 256 + threadIdx.x;
        float4 f0 = input[t * 2];
        float4 f1 = input[t * 2 + 1];
        __half2 h[4];
        h[0] = __floats2half2_rn(f0.x, f0.y);
        h[1] = __floats2half2_rn(f0.z, f0.w);
        h[2] = __floats2half2_rn(f1.x, f1.y);
        h[3] = __floats2half2_rn(f1.z, f1.w);
        *(reinterpret_cast<uint4*>(g_Bh) + t) = *reinterpret_cast<uint4*>(h);
    }
}

// ===========================================================================
// GEMM + tail-zero kernel (1D grid):
//   bid < 1024          : fp16 mma.sync 128x128 GEMM tile, scatter epilogue
//   bid in [1024, 1536) : zero 16 dense output rows if inactive (runs in the
//                         GEMM's last-wave idle slots -> nearly free)
// ===========================================================================
#define MT      128
#define NT      128
#define KC      64
#define KITERS  (K_ACT / KC)          // 32
#define STAGES  3
#define STRH    72                    // halves per smem row (144 B)
#define ROWB    (STRH * 2)            // 144 bytes
#define A_BYTES (MT * ROWB)           // 18432
#define B_BYTES (NT * ROWB)           // 18432
#define STG_BYTES (A_BYTES + B_BYTES) // 36864
#define SMEM_DYN (STAGES * STG_BYTES) // 110592 B -> 2 CTAs/SM (216 KB)
#define GEMM_BLKS ((N_TOK / NT) * (O_DIM / MT))   // 1024
#define ZERO_BLKS 512
#define ROWS_PER_ZBLK (M_DENSE / ZERO_BLKS)       // 16

__device__ __forceinline__ uint32_t smem_u32(const void* p) {
    uint32_t a;
    asm("{ .reg .u64 t; cvta.to.shared.u64 t, %1; cvt.u32.u64 %0, t; }"
        : "=r"(a) : "l"(p));
    return a;
}
__device__ __forceinline__ void ldsm_x4(uint32_t* r, uint32_t addr) {
    asm volatile("ldmatrix.sync.aligned.m8n8.x4.shared.b16 {%0,%1,%2,%3}, [%4];"
                 : "=r"(r[0]), "=r"(r[1]), "=r"(r[2]), "=r"(r[3]) : "r"(addr));
}
__device__ __forceinline__ void mma_f16(float* c, const uint32_t* a,
                                        uint32_t b0, uint32_t b1) {
    asm volatile(
        "mma.sync.aligned.m16n8k16.row.col.f32.f16.f16.f32 "
        "{%0,%1,%2,%3}, {%4,%5,%6,%7}, {%8,%9}, {%0,%1,%2,%3};"
        : "+f"(c[0]), "+f"(c[1]), "+f"(c[2]), "+f"(c[3])
        : "r"(a[0]), "r"(a[1]), "r"(a[2]), "r"(a[3]), "r"(b0), "r"(b1));
}
__device__ __forceinline__ void cp_async16(void* dst_smem, const void* src) {
    uint32_t d;
    asm("{ .reg .u64 t; cvta.to.shared.u64 t, %1; cvt.u32.u64 %0, t; }"
        : "=r"(d) : "l"(dst_smem));
    asm volatile("cp.async.cg.shared.global [%0], [%1], 16;" :: "r"(d), "l"(src));
}

__global__ __launch_bounds__(256, 2)
void gemm_mma_kernel(const int* __restrict__ indices,
                     float*     __restrict__ out) {
    const int bid = blockIdx.x;
    const int tid = threadIdx.x;

    if (bid >= GEMM_BLKS) {
        // ---- tail blocks: zero inactive output rows ----
        int row0 = (bid - GEMM_BLKS) * ROWS_PER_ZBLK;
        for (int r = 0; r < ROWS_PER_ZBLK; r++) {
            int row = row0 + r;
            int lo = 0, hi = O_DIM;
            while (lo < hi) {
                int mid = (lo + hi) >> 1;
                if (__ldg(indices + mid) < row) lo = mid + 1; else hi = mid;
            }
            if (lo < O_DIM && __ldg(indices + lo) == row) continue;  // active
            float4 z = make_float4(0.f, 0.f, 0.f, 0.f);
            float4* p = reinterpret_cast<float4*>(out + (size_t)row * N_TOK);
#pragma unroll
            for (int i = 0; i < N_TOK / 4 / 256; i++)
                p[i * 256 + tid] = z;
        }
        return;
    }

    extern __shared__ char smem[];
    const __half* Ag = g_Wh;
    const __half* Bg = g_Bh;

    const int lane = tid & 31;
    const int wid  = tid >> 5;
    const int wm   = wid >> 1;        // 0..3 -> m offset wm*32
    const int wn   = wid & 1;         // 0..1 -> n offset wn*64
    const int bm   = (bid >> 5) * MT;
    const int bn   = (bid & 31) * NT;

    // prefetch epilogue scatter rows (latency hidden behind whole mainloop)
    const int r0a = bm + wm * 32 + (lane >> 2);
    const int o_r0 = __ldg(indices + r0a);
    const int o_r8 = __ldg(indices + r0a + 8);
    const int o_r16 = __ldg(indices + r0a + 16);
    const int o_r24 = __ldg(indices + r0a + 24);

    float acc[2][8][4];
#pragma unroll
    for (int mi = 0; mi < 2; mi++)
#pragma unroll
        for (int ni = 0; ni < 8; ni++)
#pragma unroll
            for (int q = 0; q < 4; q++) acc[mi][ni][q] = 0.0f;

    // cp.async stage loader: A 128x64h, B 128x64h; 8 halves (16B) per op
    auto load_stage = [&](int kc, int s) {
        char* As = smem + s * STG_BYTES;
        char* Bs = As + A_BYTES;
#pragma unroll
        for (int i = 0; i < 4; i++) {               // A: 1024 ops
            int f = i * 256 + tid;
            int row = f >> 3, c = (f & 7) << 3;     // halves
            cp_async16(As + row * ROWB + c * 2,
                       Ag + (size_t)(bm + row) * K_ACT + kc * KC + c);
        }
#pragma unroll
        for (int i = 0; i < 4; i++) {               // B: 1024 ops
            int f = i * 256 + tid;
            int row = f >> 3, c = (f & 7) << 3;
            cp_async16(Bs + row * ROWB + c * 2,
                       Bg + (size_t)(bn + row) * K_ACT + kc * KC + c);
        }
    };

    // ldmatrix per-lane row addressing (byte offsets)
    const uint32_t smem_b = smem_u32(smem);
    const int a_row  = wm * 32 + (lane & 7) + (lane & 8);
    const int a_koff = (lane >> 4) << 3;            // halves
    const int b_row  = wn * 64 + (lane & 7) + ((lane >> 4) << 3);
    const int b_koff = (lane & 8);                  // halves

    // prologue: stages 0 and 1 in flight
    load_stage(0, 0);
    asm volatile("cp.async.commit_group;" ::: "memory");
    load_stage(1, 1);
    asm volatile("cp.async.commit_group;" ::: "memory");

    int s_cur = 0, s_nxt = 2;
    for (int kc = 0; kc < KITERS; kc++) {
        asm volatile("cp.async.wait_group 1;" ::: "memory");   // stage kc ready
        __syncthreads();   // all warps done with compute(kc-1) -> slot s_nxt free

        if (kc + 2 < KITERS) load_stage(kc + 2, s_nxt);
        asm volatile("cp.async.commit_group;" ::: "memory");

        const uint32_t As = smem_b + s_cur * STG_BYTES;
        const uint32_t Bs = As + A_BYTES;
        const uint32_t aAddr = As + a_row * ROWB + a_koff * 2;
        const uint32_t bAddr = Bs + b_row * ROWB + b_koff * 2;

#pragma unroll
        for (int ks = 0; ks < 4; ks++) {
            const int k0b = ks * 32;                // k16 * 2 bytes
            uint32_t aa[2][4];
#pragma unroll
            for (int mi = 0; mi < 2; mi++)
                ldsm_x4(aa[mi], aAddr + mi * 16 * ROWB + k0b);
            uint32_t bb[4][4];
#pragma unroll
            for (int pr = 0; pr < 4; pr++)
                ldsm_x4(bb[pr], bAddr + pr * 16 * ROWB + k0b);
#pragma unroll
            for (int mi = 0; mi < 2; mi++)
#pragma unroll
                for (int ni = 0; ni < 8; ni++)
                    mma_f16(acc[mi][ni], aa[mi],
                            bb[ni >> 1][(ni & 1) * 2],
                            bb[ni >> 1][(ni & 1) * 2 + 1]);
        }
        s_cur = (s_cur + 1 == STAGES) ? 0 : s_cur + 1;
        s_nxt = (s_nxt + 1 == STAGES) ? 0 : s_nxt + 1;
    }

    // ---- epilogue: scatter rows via prefetched indices ----
    const int orow[2][2] = {{o_r0, o_r8}, {o_r16, o_r24}};
#pragma unroll
    for (int mi = 0; mi < 2; mi++) {
        float* d0 = out + (size_t)orow[mi][0] * N_TOK + bn + wn * 64 + 2 * (lane & 3);
        float* d1 = out + (size_t)orow[mi][1] * N_TOK + bn + wn * 64 + 2 * (lane & 3);
#pragma unroll
        for (int ni = 0; ni < 8; ni++) {
            float2 v0 = make_float2(acc[mi][ni][0], acc[mi][ni][1]);
            float2 v1 = make_float2(acc[mi][ni][2], acc[mi][ni][3]);
            *reinterpret_cast<float2*>(d0 + ni * 8) = v0;
            *reinterpret_cast<float2*>(d1 + ni * 8) = v1;
        }
    }
}

// ===========================================================================
// Host launcher
// ===========================================================================
extern "C" void kernel_launch(void* const* d_in, const int* in_sizes, int n_in,
                              void* d_out, int out_size) {
    const float* input    = (const float*)d_in[0];
    const int*   idx      = (const int*)  d_in[1];
    const float* weight   = (const float*)d_in[2];
    const int*   indices  = (const int*)  d_in[3];
    const int*   metadata = (const int*)  d_in[4];
    if (in_sizes[1] == O_DIM && in_sizes[3] == K_ACT) {
        const int* t = idx; idx = indices; indices = t;
    }
    float* out = (float*)d_out;

    cudaFuncSetAttribute(gemm_mma_kernel,
                         cudaFuncAttributeMaxDynamicSharedMemorySize, SMEM_DYN);

    // 1) fused prep: gather+convert weight, convert activations
    prep_kernel<<<PREP_GRID, 256>>>(weight, idx, metadata, (const float4*)input);
    // 2) GEMM (1024 blocks) + tail zeroing (512 blocks) in one launch
    gemm_mma_kernel<<<GEMM_BLKS + ZERO_BLKS, 256, SMEM_DYN>>>(indices, out);
}

// round 13
// speedup vs baseline: 1.0081x; 1.0081x over previous
#include <cuda_runtime.h>
#include <cuda_fp16.h>
#include <cstdint>

// Problem dims (fixed by the dataset)
#define O_DIM   4096
#define I_DIM   2048
#define K_ACT   2048
#define N_TOK   4096
#define M_DENSE 8192

// Scratch (device globals; allocation-free rule): fp16 operands
__device__ __half g_Wh[(size_t)O_DIM * K_ACT];   // gathered weight, fp16
__device__ __half g_Bh[(size_t)N_TOK * K_ACT];   // activations, fp16

// ===========================================================================
// Fused prep mega-kernel: three independent jobs, branch on blockIdx.x.
//   [0, 4096)        : gather weight -> Wh (8 elems/thread, latency-bound)
//   [4096, 8192)     : fp16-convert activations (BW-bound)
//   [8192, 16384)    : zero inactive output rows (BW-bound)
// Latency-bound and BW-bound blocks co-schedule -> overlap.
// ===========================================================================
#define PREP_G1 4096
#define PREP_G2 4096
#define PREP_G3 8192
#define PREP_GRID (PREP_G1 + PREP_G2 + PREP_G3)

__global__ __launch_bounds__(256)
void prep_kernel(const float* __restrict__ weight,
                 const int*   __restrict__ idx,
                 const int*   __restrict__ metadata,
                 const float4* __restrict__ input,
                 float4*      __restrict__ out,
                 const int*   __restrict__ indices) {
    int blk = blockIdx.x;
    if (blk < PREP_G1) {
        // ---- gather compressed weight -> Wh[o][j], fp16, 8 elems/thread ----
        int t  = blk * 256 + threadIdx.x;   // group of 8 (o, j)
        int o  = t >> 8;                     // 256 groups per o-row
        int j0 = (t & 255) << 3;
        const int4 kdA = *reinterpret_cast<const int4*>(idx + j0);
        const int4 kdB = *reinterpret_cast<const int4*>(idx + j0 + 4);
        const int* md_row = metadata + (size_t)o * I_DIM;
        const float* w_row = weight + (size_t)o * I_DIM;
        int kd[8] = {kdA.x, kdA.y, kdA.z, kdA.w, kdB.x, kdB.y, kdB.z, kdB.w};
        float v[8];
#pragma unroll
        for (int e = 0; e < 8; e++) {
            int g = kd[e] >> 2;
            int p = kd[e] & 3;
            int2 md = *reinterpret_cast<const int2*>(md_row + 2 * g);
            float r = 0.0f;
            if (md.x == p)      r = __ldg(w_row + 2 * g);
            else if (md.y == p) r = __ldg(w_row + 2 * g + 1);
            v[e] = r;
        }
        __half2 h[4];
        h[0] = __floats2half2_rn(v[0], v[1]);
        h[1] = __floats2half2_rn(v[2], v[3]);
        h[2] = __floats2half2_rn(v[4], v[5]);
        h[3] = __floats2half2_rn(v[6], v[7]);
        *reinterpret_cast<uint4*>(g_Wh + (size_t)o * K_ACT + j0) =
            *reinterpret_cast<uint4*>(h);
    } else if (blk < PREP_G1 + PREP_G2) {
        // ---- fp16-convert activations: 8 floats/thread ----
        int t = (blk - PREP_G1) * 256 + threadIdx.x;
        float4 f0 = input[t * 2];
        float4 f1 = input[t * 2 + 1];
        __half2 h[4];
        h[0] = __floats2half2_rn(f0.x, f0.y);
        h[1] = __floats2half2_rn(f0.z, f0.w);
        h[2] = __floats2half2_rn(f1.x, f1.y);
        h[3] = __floats2half2_rn(f1.z, f1.w);
        *(reinterpret_cast<uint4*>(g_Bh) + t) = *reinterpret_cast<uint4*>(h);
    } else {
        // ---- zero inactive output row (active rows rewritten by GEMM) ----
        int row = blk - (PREP_G1 + PREP_G2);
        int lo = 0, hi = O_DIM;
        while (lo < hi) {
            int mid = (lo + hi) >> 1;
            if (__ldg(indices + mid) < row) lo = mid + 1; else hi = mid;
        }
        if (lo < O_DIM && __ldg(indices + lo) == row) return;   // active
        float4 z = make_float4(0.f, 0.f, 0.f, 0.f);
        float4* p = out + (size_t)row * (N_TOK / 4);
#pragma unroll
        for (int i = 0; i < N_TOK / 4 / 256; i++)
            p[i * 256 + threadIdx.x] = z;
    }
}

// ===========================================================================
// fp16 mma.sync m16n8k16 GEMM with row-scatter epilogue
//   CTA 128x128, KC=64 halves, 256 thr = 8 warps (4m x 2n), warp tile 32x64.
//   3-stage cp.async circular buffer, ONE __syncthreads per K-chunk.
// ===========================================================================
#define MT      128
#define NT      128
#define KC      64
#define KITERS  (K_ACT / KC)          // 32
#define STAGES  3
#define STRH    72                    // halves per smem row (144 B)
#define ROWB    (STRH * 2)            // 144 bytes
#define A_BYTES (MT * ROWB)           // 18432
#define B_BYTES (NT * ROWB)           // 18432
#define STG_BYTES (A_BYTES + B_BYTES) // 36864
#define SMEM_DYN (STAGES * STG_BYTES) // 110592 B -> 2 CTAs/SM (216 KB)

__device__ __forceinline__ uint32_t smem_u32(const void* p) {
    uint32_t a;
    asm("{ .reg .u64 t; cvta.to.shared.u64 t, %1; cvt.u32.u64 %0, t; }"
        : "=r"(a) : "l"(p));
    return a;
}
__device__ __forceinline__ void ldsm_x4(uint32_t* r, uint32_t addr) {
    asm volatile("ldmatrix.sync.aligned.m8n8.x4.shared.b16 {%0,%1,%2,%3}, [%4];"
                 : "=r"(r[0]), "=r"(r[1]), "=r"(r[2]), "=r"(r[3]) : "r"(addr));
}
__device__ __forceinline__ void mma_f16(float* c, const uint32_t* a,
                                        uint32_t b0, uint32_t b1) {
    asm volatile(
        "mma.sync.aligned.m16n8k16.row.col.f32.f16.f16.f32 "
        "{%0,%1,%2,%3}, {%4,%5,%6,%7}, {%8,%9}, {%0,%1,%2,%3};"
        : "+f"(c[0]), "+f"(c[1]), "+f"(c[2]), "+f"(c[3])
        : "r"(a[0]), "r"(a[1]), "r"(a[2]), "r"(a[3]), "r"(b0), "r"(b1));
}
__device__ __forceinline__ void cp_async16(void* dst_smem, const void* src) {
    uint32_t d;
    asm("{ .reg .u64 t; cvta.to.shared.u64 t, %1; cvt.u32.u64 %0, t; }"
        : "=r"(d) : "l"(dst_smem));
    asm volatile("cp.async.cg.shared.global [%0], [%1], 16;" :: "r"(d), "l"(src));
}

__global__ __launch_bounds__(256, 2)
void gemm_mma_kernel(const int* __restrict__ indices,
                     float*     __restrict__ out) {
    extern __shared__ char smem[];
    const __half* Ag = g_Wh;
    const __half* Bg = g_Bh;

    const int tid  = threadIdx.x;
    const int lane = tid & 31;
    const int wid  = tid >> 5;
    const int wm   = wid >> 1;        // 0..3 -> m offset wm*32
    const int wn   = wid & 1;         // 0..1 -> n offset wn*64
    const int bm   = blockIdx.y * MT;
    const int bn   = blockIdx.x * NT;

    // prefetch epilogue scatter rows (latency hidden behind whole mainloop)
    const int r0a = bm + wm * 32 + (lane >> 2);
    const int o_r0  = __ldg(indices + r0a);
    const int o_r8  = __ldg(indices + r0a + 8);
    const int o_r16 = __ldg(indices + r0a + 16);
    const int o_r24 = __ldg(indices + r0a + 24);

    float acc[2][8][4];
#pragma unroll
    for (int mi = 0; mi < 2; mi++)
#pragma unroll
        for (int ni = 0; ni < 8; ni++)
#pragma unroll
            for (int q = 0; q < 4; q++) acc[mi][ni][q] = 0.0f;

    // cp.async stage loader: A 128x64h, B 128x64h; 8 halves (16B) per op
    auto load_stage = [&](int kc, int s) {
        char* As = smem + s * STG_BYTES;
        char* Bs = As + A_BYTES;
#pragma unroll
        for (int i = 0; i < 4; i++) {               // A: 1024 ops
            int f = i * 256 + tid;
            int row = f >> 3, c = (f & 7) << 3;     // halves
            cp_async16(As + row * ROWB + c * 2,
                       Ag + (size_t)(bm + row) * K_ACT + kc * KC + c);
        }
#pragma unroll
        for (int i = 0; i < 4; i++) {               // B: 1024 ops
            int f = i * 256 + tid;
            int row = f >> 3, c = (f & 7) << 3;
            cp_async16(Bs + row * ROWB + c * 2,
                       Bg + (size_t)(bn + row) * K_ACT + kc * KC + c);
        }
    };

    // ldmatrix per-lane row addressing (byte offsets)
    const uint32_t smem_b = smem_u32(smem);
    const int a_row  = wm * 32 + (lane & 7) + (lane & 8);
    const int a_koff = (lane >> 4) << 3;            // halves
    const int b_row  = wn * 64 + (lane & 7) + ((lane >> 4) << 3);
    const int b_koff = (lane & 8);                  // halves

    // prologue: stages 0 and 1 in flight
    load_stage(0, 0);
    asm volatile("cp.async.commit_group;" ::: "memory");
    load_stage(1, 1);
    asm volatile("cp.async.commit_group;" ::: "memory");

    int s_cur = 0, s_nxt = 2;
    for (int kc = 0; kc < KITERS; kc++) {
        asm volatile("cp.async.wait_group 1;" ::: "memory");   // stage kc ready
        __syncthreads();   // all warps done with compute(kc-1) -> slot s_nxt free

        if (kc + 2 < KITERS) load_stage(kc + 2, s_nxt);
        asm volatile("cp.async.commit_group;" ::: "memory");

        const uint32_t As = smem_b + s_cur * STG_BYTES;
        const uint32_t Bs = As + A_BYTES;
        const uint32_t aAddr = As + a_row * ROWB + a_koff * 2;
        const uint32_t bAddr = Bs + b_row * ROWB + b_koff * 2;

#pragma unroll
        for (int ks = 0; ks < 4; ks++) {
            const int k0b = ks * 32;                // k16 * 2 bytes
            uint32_t aa[2][4];
#pragma unroll
            for (int mi = 0; mi < 2; mi++)
                ldsm_x4(aa[mi], aAddr + mi * 16 * ROWB + k0b);
            uint32_t bb[4][4];
#pragma unroll
            for (int pr = 0; pr < 4; pr++)
                ldsm_x4(bb[pr], bAddr + pr * 16 * ROWB + k0b);
#pragma unroll
            for (int mi = 0; mi < 2; mi++)
#pragma unroll
                for (int ni = 0; ni < 8; ni++)
                    mma_f16(acc[mi][ni], aa[mi],
                            bb[ni >> 1][(ni & 1) * 2],
                            bb[ni >> 1][(ni & 1) * 2 + 1]);
        }
        s_cur = (s_cur + 1 == STAGES) ? 0 : s_cur + 1;
        s_nxt = (s_nxt + 1 == STAGES) ? 0 : s_nxt + 1;
    }

    // ---- epilogue: scatter rows via prefetched indices ----
    const int orow[2][2] = {{o_r0, o_r8}, {o_r16, o_r24}};
#pragma unroll
    for (int mi = 0; mi < 2; mi++) {
        float* d0 = out + (size_t)orow[mi][0] * N_TOK + bn + wn * 64 + 2 * (lane & 3);
        float* d1 = out + (size_t)orow[mi][1] * N_TOK + bn + wn * 64 + 2 * (lane & 3);
#pragma unroll
        for (int ni = 0; ni < 8; ni++) {
            float2 v0 = make_float2(acc[mi][ni][0], acc[mi][ni][1]);
            float2 v1 = make_float2(acc[mi][ni][2], acc[mi][ni][3]);
            *reinterpret_cast<float2*>(d0 + ni * 8) = v0;
            *reinterpret_cast<float2*>(d1 + ni * 8) = v1;
        }
    }
}

// ===========================================================================
// Host launcher
// ===========================================================================
extern "C" void kernel_launch(void* const* d_in, const int* in_sizes, int n_in,
                              void* d_out, int out_size) {
    const float* input    = (const float*)d_in[0];
    const int*   idx      = (const int*)  d_in[1];
    const float* weight   = (const float*)d_in[2];
    const int*   indices  = (const int*)  d_in[3];
    const int*   metadata = (const int*)  d_in[4];
    if (in_sizes[1] == O_DIM && in_sizes[3] == K_ACT) {
        const int* t = idx; idx = indices; indices = t;
    }
    float* out = (float*)d_out;

    cudaFuncSetAttribute(gemm_mma_kernel,
                         cudaFuncAttributeMaxDynamicSharedMemorySize, SMEM_DYN);

    // 1) fused prep: gather+convert weight (8/thread), convert acts, zero rows
    prep_kernel<<<PREP_GRID, 256>>>(weight, idx, metadata,
                                    (const float4*)input, (float4*)out, indices);
    // 2) tensor-core GEMM + scatter
    dim3 grid(N_TOK / NT, O_DIM / MT);   // 32 x 32
    gemm_mma_kernel<<<grid, 256, SMEM_DYN>>>(indices, out);
}

// round 14
// speedup vs baseline: 1.1689x; 1.1596x over previous
#include <cuda_runtime.h>
#include <cuda_fp16.h>
#include <cstdint>

// Problem dims (fixed by the dataset)
#define O_DIM   4096
#define I_DIM   2048
#define K_ACT   2048
#define N_TOK   4096
#define M_DENSE 8192

// Scratch (device globals; allocation-free rule): fp16 operands
__device__ __half g_Wh[(size_t)O_DIM * K_ACT];   // gathered weight, fp16
__device__ __half g_Bh[(size_t)N_TOK * K_ACT];   // activations, fp16

// ===========================================================================
// Fused prep mega-kernel (R11 form): three jobs, branch on blockIdx.x.
//   [0, 8192)        : gather weight -> Wh (4 elems/thread, latency-bound)
//   [8192, 12288)    : fp16-convert activations (BW-bound)
//   [12288, 20480)   : zero inactive output rows (BW-bound)
// ===========================================================================
#define PREP_G1 8192
#define PREP_G2 4096
#define PREP_G3 8192
#define PREP_GRID (PREP_G1 + PREP_G2 + PREP_G3)

__global__ __launch_bounds__(256)
void prep_kernel(const float* __restrict__ weight,
                 const int*   __restrict__ idx,
                 const int*   __restrict__ metadata,
                 const float4* __restrict__ input,
                 float4*      __restrict__ out,
                 const int*   __restrict__ indices) {
    int blk = blockIdx.x;
    if (blk < PREP_G1) {
        // ---- gather compressed weight -> Wh[o][j], fp16, 4 elems/thread ----
        int t  = blk * 256 + threadIdx.x;
        int o  = t >> 9;
        int j0 = (t & 511) << 2;
        const int4 kd4 = *reinterpret_cast<const int4*>(idx + j0);
        const int* md_row = metadata + (size_t)o * I_DIM;
        const float* w_row = weight + (size_t)o * I_DIM;
        int kd[4] = {kd4.x, kd4.y, kd4.z, kd4.w};
        float v[4];
#pragma unroll
        for (int e = 0; e < 4; e++) {
            int g = kd[e] >> 2;
            int p = kd[e] & 3;
            int2 md = *reinterpret_cast<const int2*>(md_row + 2 * g);
            float r = 0.0f;
            if (md.x == p)      r = __ldg(w_row + 2 * g);
            else if (md.y == p) r = __ldg(w_row + 2 * g + 1);
            v[e] = r;
        }
        __half2 h01 = __floats2half2_rn(v[0], v[1]);
        __half2 h23 = __floats2half2_rn(v[2], v[3]);
        uint2 pack;
        pack.x = *reinterpret_cast<uint32_t*>(&h01);
        pack.y = *reinterpret_cast<uint32_t*>(&h23);
        *reinterpret_cast<uint2*>(g_Wh + (size_t)o * K_ACT + j0) = pack;
    } else if (blk < PREP_G1 + PREP_G2) {
        // ---- fp16-convert activations: 8 floats/thread ----
        int t = (blk - PREP_G1) * 256 + threadIdx.x;
        float4 f0 = input[t * 2];
        float4 f1 = input[t * 2 + 1];
        __half2 h[4];
        h[0] = __floats2half2_rn(f0.x, f0.y);
        h[1] = __floats2half2_rn(f0.z, f0.w);
        h[2] = __floats2half2_rn(f1.x, f1.y);
        h[3] = __floats2half2_rn(f1.z, f1.w);
        *(reinterpret_cast<uint4*>(g_Bh) + t) = *reinterpret_cast<uint4*>(h);
    } else {
        // ---- zero inactive output row (active rows rewritten by GEMM) ----
        int row = blk - (PREP_G1 + PREP_G2);
        int lo = 0, hi = O_DIM;
        while (lo < hi) {
            int mid = (lo + hi) >> 1;
            if (__ldg(indices + mid) < row) lo = mid + 1; else hi = mid;
        }
        if (lo < O_DIM && __ldg(indices + lo) == row) return;   // active
        float4 z = make_float4(0.f, 0.f, 0.f, 0.f);
        float4* p = out + (size_t)row * (N_TOK / 4);
#pragma unroll
        for (int i = 0; i < N_TOK / 4 / 256; i++)
            p[i * 256 + threadIdx.x] = z;
    }
}

// ===========================================================================
// fp16 mma.sync m16n8k16 GEMM with row-scatter epilogue
//   CTA 128x128, KC=64 halves, 256 thr = 8 warps (4m x 2n), warp tile 32x64.
//   3-stage cp.async circular buffer, ONE __syncthreads per K-chunk.
//   cp.async ops for stage kc+2 are SPREAD across the 4 ks iterations so the
//   MIO queue never sees a head-of-chunk burst competing with LDSM.
// ===========================================================================
#define MT      128
#define NT      128
#define KC      64
#define KITERS  (K_ACT / KC)          // 32
#define STAGES  3
#define STRH    72                    // halves per smem row (144 B)
#define ROWB    (STRH * 2)            // 144 bytes
#define A_BYTES (MT * ROWB)           // 18432
#define B_BYTES (NT * ROWB)           // 18432
#define STG_BYTES (A_BYTES + B_BYTES) // 36864
#define SMEM_DYN (STAGES * STG_BYTES) // 110592 B -> 2 CTAs/SM (216 KB)

__device__ __forceinline__ uint32_t smem_u32(const void* p) {
    uint32_t a;
    asm("{ .reg .u64 t; cvta.to.shared.u64 t, %1; cvt.u32.u64 %0, t; }"
        : "=r"(a) : "l"(p));
    return a;
}
__device__ __forceinline__ void ldsm_x4(uint32_t* r, uint32_t addr) {
    asm volatile("ldmatrix.sync.aligned.m8n8.x4.shared.b16 {%0,%1,%2,%3}, [%4];"
                 : "=r"(r[0]), "=r"(r[1]), "=r"(r[2]), "=r"(r[3]) : "r"(addr));
}
__device__ __forceinline__ void mma_f16(float* c, const uint32_t* a,
                                        uint32_t b0, uint32_t b1) {
    asm volatile(
        "mma.sync.aligned.m16n8k16.row.col.f32.f16.f16.f32 "
        "{%0,%1,%2,%3}, {%4,%5,%6,%7}, {%8,%9}, {%0,%1,%2,%3};"
        : "+f"(c[0]), "+f"(c[1]), "+f"(c[2]), "+f"(c[3])
        : "r"(a[0]), "r"(a[1]), "r"(a[2]), "r"(a[3]), "r"(b0), "r"(b1));
}
__device__ __forceinline__ void cp_async16(void* dst_smem, const void* src) {
    uint32_t d;
    asm("{ .reg .u64 t; cvta.to.shared.u64 t, %1; cvt.u32.u64 %0, t; }"
        : "=r"(d) : "l"(dst_smem));
    asm volatile("cp.async.cg.shared.global [%0], [%1], 16;" :: "r"(d), "l"(src));
}

__global__ __launch_bounds__(256, 2)
void gemm_mma_kernel(const int* __restrict__ indices,
                     float*     __restrict__ out) {
    extern __shared__ char smem[];
    const __half* Ag = g_Wh;
    const __half* Bg = g_Bh;

    const int tid  = threadIdx.x;
    const int lane = tid & 31;
    const int wid  = tid >> 5;
    const int wm   = wid >> 1;        // 0..3 -> m offset wm*32
    const int wn   = wid & 1;         // 0..1 -> n offset wn*64
    const int bm   = blockIdx.y * MT;
    const int bn   = blockIdx.x * NT;

    // prefetch epilogue scatter rows (latency hidden behind whole mainloop)
    const int r0a = bm + wm * 32 + (lane >> 2);
    const int o_r0  = __ldg(indices + r0a);
    const int o_r8  = __ldg(indices + r0a + 8);
    const int o_r16 = __ldg(indices + r0a + 16);
    const int o_r24 = __ldg(indices + r0a + 24);

    float acc[2][8][4];
#pragma unroll
    for (int mi = 0; mi < 2; mi++)
#pragma unroll
        for (int ni = 0; ni < 8; ni++)
#pragma unroll
            for (int q = 0; q < 4; q++) acc[mi][ni][q] = 0.0f;

    // per-thread source/destination for this thread's 8 cp.async ops
    const int ld_row = tid >> 3;                 // 0..31  (x4 row groups of 32)
    const int ld_c   = (tid & 7) << 3;           // halves

    // full-stage loader (prologue only)
    auto load_stage = [&](int kc, int s) {
        char* As = smem + s * STG_BYTES;
        char* Bs = As + A_BYTES;
#pragma unroll
        for (int i = 0; i < 4; i++) {
            int row = ld_row + i * 32;
            cp_async16(As + row * ROWB + ld_c * 2,
                       Ag + (size_t)(bm + row) * K_ACT + kc * KC + ld_c);
            cp_async16(Bs + row * ROWB + ld_c * 2,
                       Bg + (size_t)(bn + row) * K_ACT + kc * KC + ld_c);
        }
    };

    // ldmatrix per-lane row addressing (byte offsets)
    const uint32_t smem_b = smem_u32(smem);
    const int a_row  = wm * 32 + (lane & 7) + (lane & 8);
    const int a_koff = (lane >> 4) << 3;            // halves
    const int b_row  = wn * 64 + (lane & 7) + ((lane >> 4) << 3);
    const int b_koff = (lane & 8);                  // halves

    // prologue: stages 0 and 1 in flight
    load_stage(0, 0);
    asm volatile("cp.async.commit_group;" ::: "memory");
    load_stage(1, 1);
    asm volatile("cp.async.commit_group;" ::: "memory");

    int s_cur = 0, s_nxt = 2;
    for (int kc = 0; kc < KITERS; kc++) {
        asm volatile("cp.async.wait_group 1;" ::: "memory");   // stage kc ready
        __syncthreads();   // all warps done with compute(kc-1) -> slot s_nxt free

        const bool do_load = (kc + 2 < KITERS);
        char* Asn = smem + s_nxt * STG_BYTES;
        char* Bsn = Asn + A_BYTES;
        const __half* Agn = Ag + (size_t)bm * K_ACT + (kc + 2) * KC;
        const __half* Bgn = Bg + (size_t)bn * K_ACT + (kc + 2) * KC;

        const uint32_t As = smem_b + s_cur * STG_BYTES;
        const uint32_t Bs = As + A_BYTES;
        const uint32_t aAddr = As + a_row * ROWB + a_koff * 2;
        const uint32_t bAddr = Bs + b_row * ROWB + b_koff * 2;

#pragma unroll
        for (int ks = 0; ks < 4; ks++) {
            // 2 of this thread's 8 next-stage cp.async ops, spread per ks
            if (do_load) {
                int row = ld_row + ks * 32;
                cp_async16(Asn + row * ROWB + ld_c * 2,
                           Agn + (size_t)row * K_ACT + ld_c);
                cp_async16(Bsn + row * ROWB + ld_c * 2,
                           Bgn + (size_t)row * K_ACT + ld_c);
            }
            const int k0b = ks * 32;                // k16 * 2 bytes
            uint32_t aa[2][4];
#pragma unroll
            for (int mi = 0; mi < 2; mi++)
                ldsm_x4(aa[mi], aAddr + mi * 16 * ROWB + k0b);
            uint32_t bb[4][4];
#pragma unroll
            for (int pr = 0; pr < 4; pr++)
                ldsm_x4(bb[pr], bAddr + pr * 16 * ROWB + k0b);
#pragma unroll
            for (int mi = 0; mi < 2; mi++)
#pragma unroll
                for (int ni = 0; ni < 8; ni++)
                    mma_f16(acc[mi][ni], aa[mi],
                            bb[ni >> 1][(ni & 1) * 2],
                            bb[ni >> 1][(ni & 1) * 2 + 1]);
        }
        asm volatile("cp.async.commit_group;" ::: "memory");   // stage kc+2 group
        s_cur = (s_cur + 1 == STAGES) ? 0 : s_cur + 1;
        s_nxt = (s_nxt + 1 == STAGES) ? 0 : s_nxt + 1;
    }

    // ---- epilogue: scatter rows via prefetched indices ----
    const int orow[2][2] = {{o_r0, o_r8}, {o_r16, o_r24}};
#pragma unroll
    for (int mi = 0; mi < 2; mi++) {
        float* d0 = out + (size_t)orow[mi][0] * N_TOK + bn + wn * 64 + 2 * (lane & 3);
        float* d1 = out + (size_t)orow[mi][1] * N_TOK + bn + wn * 64 + 2 * (lane & 3);
#pragma unroll
        for (int ni = 0; ni < 8; ni++) {
            float2 v0 = make_float2(acc[mi][ni][0], acc[mi][ni][1]);
            float2 v1 = make_float2(acc[mi][ni][2], acc[mi][ni][3]);
            *reinterpret_cast<float2*>(d0 + ni * 8) = v0;
            *reinterpret_cast<float2*>(d1 + ni * 8) = v1;
        }
    }
}

// ===========================================================================
// Host launcher
// ===========================================================================
extern "C" void kernel_launch(void* const* d_in, const int* in_sizes, int n_in,
                              void* d_out, int out_size) {
    const float* input    = (const float*)d_in[0];
    const int*   idx      = (const int*)  d_in[1];
    const float* weight   = (const float*)d_in[2];
    const int*   indices  = (const int*)  d_in[3];
    const int*   metadata = (const int*)  d_in[4];
    if (in_sizes[1] == O_DIM && in_sizes[3] == K_ACT) {
        const int* t = idx; idx = indices; indices = t;
    }
    float* out = (float*)d_out;

    cudaFuncSetAttribute(gemm_mma_kernel,
                         cudaFuncAttributeMaxDynamicSharedMemorySize, SMEM_DYN);

    // 1) fused prep: gather+convert weight, convert activations, zero rows
    prep_kernel<<<PREP_GRID, 256>>>(weight, idx, metadata,
                                    (const float4*)input, (float4*)out, indices);
    // 2) tensor-core GEMM + scatter
    dim3 grid(N_TOK / NT, O_DIM / MT);   // 32 x 32
    gemm_mma_kernel<<<grid, 256, SMEM_DYN>>>(indices, out);
}

// round 15
// speedup vs baseline: 1.1749x; 1.0051x over previous
#include <cuda_runtime.h>
#include <cuda_fp16.h>
#include <cstdint>

// Problem dims (fixed by the dataset)
#define O_DIM   4096
#define I_DIM   2048
#define K_ACT   2048
#define N_TOK   4096
#define M_DENSE 8192

// Scratch (device globals; allocation-free rule): fp16 operands
__device__ __half g_Wh[(size_t)O_DIM * K_ACT];   // gathered weight, fp16
__device__ __half g_Bh[(size_t)N_TOK * K_ACT];   // activations, fp16

// ===========================================================================
// Fused prep kernel: two jobs, branch on blockIdx.x.
//   [0, 8192)      : gather weight -> Wh (4 elems/thread, latency-bound)
//   [8192, 12288)  : fp16-convert activations (BW-bound)
// (inactive-row zeroing is distributed into the GEMM epilogue)
// ===========================================================================
#define PREP_G1 8192
#define PREP_G2 4096
#define PREP_GRID (PREP_G1 + PREP_G2)

__global__ __launch_bounds__(256)
void prep_kernel(const float* __restrict__ weight,
                 const int*   __restrict__ idx,
                 const int*   __restrict__ metadata,
                 const float4* __restrict__ input) {
    int blk = blockIdx.x;
    if (blk < PREP_G1) {
        // ---- gather compressed weight -> Wh[o][j], fp16, 4 elems/thread ----
        int t  = blk * 256 + threadIdx.x;
        int o  = t >> 9;
        int j0 = (t & 511) << 2;
        const int4 kd4 = *reinterpret_cast<const int4*>(idx + j0);
        const int* md_row = metadata + (size_t)o * I_DIM;
        const float* w_row = weight + (size_t)o * I_DIM;
        int kd[4] = {kd4.x, kd4.y, kd4.z, kd4.w};
        float v[4];
#pragma unroll
        for (int e = 0; e < 4; e++) {
            int g = kd[e] >> 2;
            int p = kd[e] & 3;
            int2 md = *reinterpret_cast<const int2*>(md_row + 2 * g);
            float r = 0.0f;
            if (md.x == p)      r = __ldg(w_row + 2 * g);
            else if (md.y == p) r = __ldg(w_row + 2 * g + 1);
            v[e] = r;
        }
        __half2 h01 = __floats2half2_rn(v[0], v[1]);
        __half2 h23 = __floats2half2_rn(v[2], v[3]);
        uint2 pack;
        pack.x = *reinterpret_cast<uint32_t*>(&h01);
        pack.y = *reinterpret_cast<uint32_t*>(&h23);
        *reinterpret_cast<uint2*>(g_Wh + (size_t)o * K_ACT + j0) = pack;
    } else {
        // ---- fp16-convert activations: 8 floats/thread ----
        int t = (blk - PREP_G1) * 256 + threadIdx.x;
        float4 f0 = input[t * 2];
        float4 f1 = input[t * 2 + 1];
        __half2 h[4];
        h[0] = __floats2half2_rn(f0.x, f0.y);
        h[1] = __floats2half2_rn(f0.z, f0.w);
        h[2] = __floats2half2_rn(f1.x, f1.y);
        h[3] = __floats2half2_rn(f1.z, f1.w);
        *(reinterpret_cast<uint4*>(g_Bh) + t) = *reinterpret_cast<uint4*>(h);
    }
}

// ===========================================================================
// fp16 mma.sync m16n8k16 GEMM with row-scatter epilogue + distributed zeroing
//   CTA 128x128, KC=64 halves, 256 thr = 8 warps (4m x 2n), warp tile 32x64.
//   3-stage cp.async circular buffer, ONE __syncthreads per K-chunk.
//   cp.async ops for stage kc+2 spread across ks, issued AFTER the LDSMs.
//   Epilogue also zeroes the inactive dense rows of this CTA's m-interval
//   within its 128-column stripe (disjoint, covering partition).
// ===========================================================================
#define MT      128
#define NT      128
#define KC      64
#define KITERS  (K_ACT / KC)          // 32
#define STAGES  3
#define STRH    72                    // halves per smem row (144 B)
#define ROWB    (STRH * 2)            // 144 bytes
#define A_BYTES (MT * ROWB)           // 18432
#define B_BYTES (NT * ROWB)           // 18432
#define STG_BYTES (A_BYTES + B_BYTES) // 36864
#define SMEM_DYN (STAGES * STG_BYTES) // 110592 B -> 2 CTAs/SM (216 KB)

__device__ __forceinline__ uint32_t smem_u32(const void* p) {
    uint32_t a;
    asm("{ .reg .u64 t; cvta.to.shared.u64 t, %1; cvt.u32.u64 %0, t; }"
        : "=r"(a) : "l"(p));
    return a;
}
__device__ __forceinline__ void ldsm_x4(uint32_t* r, uint32_t addr) {
    asm volatile("ldmatrix.sync.aligned.m8n8.x4.shared.b16 {%0,%1,%2,%3}, [%4];"
                 : "=r"(r[0]), "=r"(r[1]), "=r"(r[2]), "=r"(r[3]) : "r"(addr));
}
__device__ __forceinline__ void mma_f16(float* c, const uint32_t* a,
                                        uint32_t b0, uint32_t b1) {
    asm volatile(
        "mma.sync.aligned.m16n8k16.row.col.f32.f16.f16.f32 "
        "{%0,%1,%2,%3}, {%4,%5,%6,%7}, {%8,%9}, {%0,%1,%2,%3};"
        : "+f"(c[0]), "+f"(c[1]), "+f"(c[2]), "+f"(c[3])
        : "r"(a[0]), "r"(a[1]), "r"(a[2]), "r"(a[3]), "r"(b0), "r"(b1));
}
__device__ __forceinline__ void cp_async16(void* dst_smem, const void* src) {
    uint32_t d;
    asm("{ .reg .u64 t; cvta.to.shared.u64 t, %1; cvt.u32.u64 %0, t; }"
        : "=r"(d) : "l"(dst_smem));
    asm volatile("cp.async.cg.shared.global [%0], [%1], 16;" :: "r"(d), "l"(src));
}

__global__ __launch_bounds__(256, 2)
void gemm_mma_kernel(const int* __restrict__ indices,
                     float*     __restrict__ out) {
    extern __shared__ char smem[];
    const __half* Ag = g_Wh;
    const __half* Bg = g_Bh;

    const int tid  = threadIdx.x;
    const int lane = tid & 31;
    const int wid  = tid >> 5;
    const int wm   = wid >> 1;        // 0..3 -> m offset wm*32
    const int wn   = wid & 1;         // 0..1 -> n offset wn*64
    const int tm   = blockIdx.y;      // m-tile index 0..31
    const int bm   = tm * MT;
    const int bn   = blockIdx.x * NT;

    // prefetch epilogue scatter rows (latency hidden behind whole mainloop)
    const int r0a = bm + wm * 32 + (lane >> 2);
    const int o_r0  = __ldg(indices + r0a);
    const int o_r8  = __ldg(indices + r0a + 8);
    const int o_r16 = __ldg(indices + r0a + 16);
    const int o_r24 = __ldg(indices + r0a + 24);
    // dense-row interval owned by this m-tile (for inactive-row zeroing)
    const int zlo = (tm == 0) ? 0 : __ldg(indices + bm - 1) + 1;
    const int zhi = (tm == (O_DIM / MT - 1)) ? M_DENSE
                                             : __ldg(indices + bm + MT - 1) + 1;

    float acc[2][8][4];
#pragma unroll
    for (int mi = 0; mi < 2; mi++)
#pragma unroll
        for (int ni = 0; ni < 8; ni++)
#pragma unroll
            for (int q = 0; q < 4; q++) acc[mi][ni][q] = 0.0f;

    // per-thread source/destination for this thread's 8 cp.async ops
    const int ld_row = tid >> 3;                 // 0..31
    const int ld_c   = (tid & 7) << 3;           // halves

    // full-stage loader (prologue only)
    auto load_stage = [&](int kc, int s) {
        char* As = smem + s * STG_BYTES;
        char* Bs = As + A_BYTES;
#pragma unroll
        for (int i = 0; i < 4; i++) {
            int row = ld_row + i * 32;
            cp_async16(As + row * ROWB + ld_c * 2,
                       Ag + (size_t)(bm + row) * K_ACT + kc * KC + ld_c);
            cp_async16(Bs + row * ROWB + ld_c * 2,
                       Bg + (size_t)(bn + row) * K_ACT + kc * KC + ld_c);
        }
    };

    // ldmatrix per-lane row addressing (byte offsets)
    const uint32_t smem_b = smem_u32(smem);
    const int a_row  = wm * 32 + (lane & 7) + (lane & 8);
    const int a_koff = (lane >> 4) << 3;            // halves
    const int b_row  = wn * 64 + (lane & 7) + ((lane >> 4) << 3);
    const int b_koff = (lane & 8);                  // halves

    // prologue: stages 0 and 1 in flight
    load_stage(0, 0);
    asm volatile("cp.async.commit_group;" ::: "memory");
    load_stage(1, 1);
    asm volatile("cp.async.commit_group;" ::: "memory");

    int s_cur = 0, s_nxt = 2;
    for (int kc = 0; kc < KITERS; kc++) {
        asm volatile("cp.async.wait_group 1;" ::: "memory");   // stage kc ready
        __syncthreads();   // all warps done with compute(kc-1) -> slot s_nxt free

        const bool do_load = (kc + 2 < KITERS);
        char* Asn = smem + s_nxt * STG_BYTES;
        char* Bsn = Asn + A_BYTES;
        const __half* Agn = Ag + (size_t)bm * K_ACT + (kc + 2) * KC;
        const __half* Bgn = Bg + (size_t)bn * K_ACT + (kc + 2) * KC;

        const uint32_t As = smem_b + s_cur * STG_BYTES;
        const uint32_t Bs = As + A_BYTES;
        const uint32_t aAddr = As + a_row * ROWB + a_koff * 2;
        const uint32_t bAddr = Bs + b_row * ROWB + b_koff * 2;

#pragma unroll
        for (int ks = 0; ks < 4; ks++) {
            const int k0b = ks * 32;                // k16 * 2 bytes
            uint32_t aa[2][4];
#pragma unroll
            for (int mi = 0; mi < 2; mi++)
                ldsm_x4(aa[mi], aAddr + mi * 16 * ROWB + k0b);
            uint32_t bb[4][4];
#pragma unroll
            for (int pr = 0; pr < 4; pr++)
                ldsm_x4(bb[pr], bAddr + pr * 16 * ROWB + k0b);
            // 2 of this thread's 8 next-stage cp.async ops, issued while the
            // LDSMs above are in flight (overlap issue cost with HMMA)
            if (do_load) {
                int row = ld_row + ks * 32;
                cp_async16(Asn + row * ROWB + ld_c * 2,
                           Agn + (size_t)row * K_ACT + ld_c);
                cp_async16(Bsn + row * ROWB + ld_c * 2,
                           Bgn + (size_t)row * K_ACT + ld_c);
            }
#pragma unroll
            for (int mi = 0; mi < 2; mi++)
#pragma unroll
                for (int ni = 0; ni < 8; ni++)
                    mma_f16(acc[mi][ni], aa[mi],
                            bb[ni >> 1][(ni & 1) * 2],
                            bb[ni >> 1][(ni & 1) * 2 + 1]);
        }
        asm volatile("cp.async.commit_group;" ::: "memory");   // stage kc+2 group
        s_cur = (s_cur + 1 == STAGES) ? 0 : s_cur + 1;
        s_nxt = (s_nxt + 1 == STAGES) ? 0 : s_nxt + 1;
    }

    // ---- epilogue 1: scatter GEMM rows via prefetched indices ----
    const int orow[2][2] = {{o_r0, o_r8}, {o_r16, o_r24}};
#pragma unroll
    for (int mi = 0; mi < 2; mi++) {
        float* d0 = out + (size_t)orow[mi][0] * N_TOK + bn + wn * 64 + 2 * (lane & 3);
        float* d1 = out + (size_t)orow[mi][1] * N_TOK + bn + wn * 64 + 2 * (lane & 3);
#pragma unroll
        for (int ni = 0; ni < 8; ni++) {
            float2 v0 = make_float2(acc[mi][ni][0], acc[mi][ni][1]);
            float2 v1 = make_float2(acc[mi][ni][2], acc[mi][ni][3]);
            *reinterpret_cast<float2*>(d0 + ni * 8) = v0;
            *reinterpret_cast<float2*>(d1 + ni * 8) = v1;
        }
    }

    // ---- epilogue 2: zero inactive dense rows of this tile's interval ----
    for (int r = zlo + tid; r < zhi; r += 256) {
        // binary search within this tile's 128 sorted active indices
        int lo = bm, hi = bm + MT;
        while (lo < hi) {
            int mid = (lo + hi) >> 1;
            if (__ldg(indices + mid) < r) lo = mid + 1; else hi = mid;
        }
        if (lo < bm + MT && __ldg(indices + lo) == r) continue;   // active row
        float4 z = make_float4(0.f, 0.f, 0.f, 0.f);
        float4* p = reinterpret_cast<float4*>(out + (size_t)r * N_TOK + bn);
#pragma unroll
        for (int i = 0; i < NT / 4; i++) p[i] = z;
    }
}

// ===========================================================================
// Host launcher
// ===========================================================================
extern "C" void kernel_launch(void* const* d_in, const int* in_sizes, int n_in,
                              void* d_out, int out_size) {
    const float* input    = (const float*)d_in[0];
    const int*   idx      = (const int*)  d_in[1];
    const float* weight   = (const float*)d_in[2];
    const int*   indices  = (const int*)  d_in[3];
    const int*   metadata = (const int*)  d_in[4];
    if (in_sizes[1] == O_DIM && in_sizes[3] == K_ACT) {
        const int* t = idx; idx = indices; indices = t;
    }
    float* out = (float*)d_out;

    cudaFuncSetAttribute(gemm_mma_kernel,
                         cudaFuncAttributeMaxDynamicSharedMemorySize, SMEM_DYN);

    // 1) fused prep: gather+convert weight, convert activations
    prep_kernel<<<PREP_GRID, 256>>>(weight, idx, metadata, (const float4*)input);
    // 2) tensor-core GEMM + scatter + distributed inactive-row zeroing
    dim3 grid(N_TOK / NT, O_DIM / MT);   // 32 x 32
    gemm_mma_kernel<<<grid, 256, SMEM_DYN>>>(indices, out);
}

// round 16
// speedup vs baseline: 1.1916x; 1.0142x over previous
#include <cuda_runtime.h>
#include <cuda_fp16.h>
#include <cstdint>

// Problem dims (fixed by the dataset)
#define O_DIM   4096
#define I_DIM   2048
#define K_ACT   2048
#define N_TOK   4096
#define M_DENSE 8192

// Scratch (device globals; allocation-free rule): fp16 operands
__device__ __half g_Wh[(size_t)O_DIM * K_ACT];   // gathered weight, fp16
__device__ __half g_Bh[(size_t)N_TOK * K_ACT];   // activations, fp16

// ===========================================================================
// Fused prep kernel: two jobs, branch on blockIdx.x.
//   [0, 8192)      : gather weight -> Wh (4 elems/thread, latency-bound)
//   [8192, 12288)  : fp16-convert activations (BW-bound)
// ===========================================================================
#define PREP_G1 8192
#define PREP_G2 4096
#define PREP_GRID (PREP_G1 + PREP_G2)

__global__ __launch_bounds__(256)
void prep_kernel(const float* __restrict__ weight,
                 const int*   __restrict__ idx,
                 const int*   __restrict__ metadata,
                 const float4* __restrict__ input) {
    int blk = blockIdx.x;
    if (blk < PREP_G1) {
        // ---- gather compressed weight -> Wh[o][j], fp16, 4 elems/thread ----
        int t  = blk * 256 + threadIdx.x;
        int o  = t >> 9;
        int j0 = (t & 511) << 2;
        const int4 kd4 = *reinterpret_cast<const int4*>(idx + j0);
        const int* md_row = metadata + (size_t)o * I_DIM;
        const float* w_row = weight + (size_t)o * I_DIM;
        int kd[4] = {kd4.x, kd4.y, kd4.z, kd4.w};
        float v[4];
#pragma unroll
        for (int e = 0; e < 4; e++) {
            int g = kd[e] >> 2;
            int p = kd[e] & 3;
            int2 md = *reinterpret_cast<const int2*>(md_row + 2 * g);
            float r = 0.0f;
            if (md.x == p)      r = __ldg(w_row + 2 * g);
            else if (md.y == p) r = __ldg(w_row + 2 * g + 1);
            v[e] = r;
        }
        __half2 h01 = __floats2half2_rn(v[0], v[1]);
        __half2 h23 = __floats2half2_rn(v[2], v[3]);
        uint2 pack;
        pack.x = *reinterpret_cast<uint32_t*>(&h01);
        pack.y = *reinterpret_cast<uint32_t*>(&h23);
        *reinterpret_cast<uint2*>(g_Wh + (size_t)o * K_ACT + j0) = pack;
    } else {
        // ---- fp16-convert activations: 8 floats/thread ----
        int t = (blk - PREP_G1) * 256 + threadIdx.x;
        float4 f0 = input[t * 2];
        float4 f1 = input[t * 2 + 1];
        __half2 h[4];
        h[0] = __floats2half2_rn(f0.x, f0.y);
        h[1] = __floats2half2_rn(f0.z, f0.w);
        h[2] = __floats2half2_rn(f1.x, f1.y);
        h[3] = __floats2half2_rn(f1.z, f1.w);
        *(reinterpret_cast<uint4*>(g_Bh) + t) = *reinterpret_cast<uint4*>(h);
    }
}

// ===========================================================================
// fp16 mma.sync m16n8k16 GEMM + scatter + distributed zeroing
//   CTA 128x128, KC=64 halves, 256 thr = 8 warps (4m x 2n), warp tile 32x64.
//   3-stage cp.async circular buffer, ONE __syncthreads per K-chunk,
//   per-ks-spread cp.async. Inactive-row zeroing runs in the PROLOGUE
//   (fire-and-forget .cs stores drain behind the whole mainloop).
//   All output stores use st.global.cs (evict-first) to protect L2 operands.
// ===========================================================================
#define MT      128
#define NT      128
#define KC      64
#define KITERS  (K_ACT / KC)          // 32
#define STAGES  3
#define STRH    72                    // halves per smem row (144 B)
#define ROWB    (STRH * 2)            // 144 bytes
#define A_BYTES (MT * ROWB)           // 18432
#define B_BYTES (NT * ROWB)           // 18432
#define STG_BYTES (A_BYTES + B_BYTES) // 36864
#define SMEM_DYN (STAGES * STG_BYTES) // 110592 B -> 2 CTAs/SM (216 KB)

__device__ __forceinline__ uint32_t smem_u32(const void* p) {
    uint32_t a;
    asm("{ .reg .u64 t; cvta.to.shared.u64 t, %1; cvt.u32.u64 %0, t; }"
        : "=r"(a) : "l"(p));
    return a;
}
__device__ __forceinline__ void ldsm_x4(uint32_t* r, uint32_t addr) {
    asm volatile("ldmatrix.sync.aligned.m8n8.x4.shared.b16 {%0,%1,%2,%3}, [%4];"
                 : "=r"(r[0]), "=r"(r[1]), "=r"(r[2]), "=r"(r[3]) : "r"(addr));
}
__device__ __forceinline__ void mma_f16(float* c, const uint32_t* a,
                                        uint32_t b0, uint32_t b1) {
    asm volatile(
        "mma.sync.aligned.m16n8k16.row.col.f32.f16.f16.f32 "
        "{%0,%1,%2,%3}, {%4,%5,%6,%7}, {%8,%9}, {%0,%1,%2,%3};"
        : "+f"(c[0]), "+f"(c[1]), "+f"(c[2]), "+f"(c[3])
        : "r"(a[0]), "r"(a[1]), "r"(a[2]), "r"(a[3]), "r"(b0), "r"(b1));
}
__device__ __forceinline__ void cp_async16(void* dst_smem, const void* src) {
    uint32_t d;
    asm("{ .reg .u64 t; cvta.to.shared.u64 t, %1; cvt.u32.u64 %0, t; }"
        : "=r"(d) : "l"(dst_smem));
    asm volatile("cp.async.cg.shared.global [%0], [%1], 16;" :: "r"(d), "l"(src));
}
__device__ __forceinline__ void stg_cs_v4(float* p, float x, float y,
                                          float z, float w) {
    asm volatile("st.global.cs.v4.f32 [%0], {%1,%2,%3,%4};"
                 :: "l"(p), "f"(x), "f"(y), "f"(z), "f"(w) : "memory");
}
__device__ __forceinline__ void stg_cs_v2(float* p, float x, float y) {
    asm volatile("st.global.cs.v2.f32 [%0], {%1,%2};"
                 :: "l"(p), "f"(x), "f"(y) : "memory");
}

__global__ __launch_bounds__(256, 2)
void gemm_mma_kernel(const int* __restrict__ indices,
                     float*     __restrict__ out) {
    extern __shared__ char smem[];
    const __half* Ag = g_Wh;
    const __half* Bg = g_Bh;

    const int tid  = threadIdx.x;
    const int lane = tid & 31;
    const int wid  = tid >> 5;
    const int wm   = wid >> 1;        // 0..3 -> m offset wm*32
    const int wn   = wid & 1;         // 0..1 -> n offset wn*64
    const int tm   = blockIdx.y;      // m-tile index 0..31
    const int bm   = tm * MT;
    const int bn   = blockIdx.x * NT;

    // prefetch epilogue scatter rows (latency hidden behind whole mainloop)
    const int r0a = bm + wm * 32 + (lane >> 2);
    const int o_r0  = __ldg(indices + r0a);
    const int o_r8  = __ldg(indices + r0a + 8);
    const int o_r16 = __ldg(indices + r0a + 16);
    const int o_r24 = __ldg(indices + r0a + 24);
    // dense-row interval owned by this m-tile (for inactive-row zeroing)
    const int zlo = (tm == 0) ? 0 : __ldg(indices + bm - 1) + 1;
    const int zhi = (tm == (O_DIM / MT - 1)) ? M_DENSE
                                             : __ldg(indices + bm + MT - 1) + 1;

    float acc[2][8][4];
#pragma unroll
    for (int mi = 0; mi < 2; mi++)
#pragma unroll
        for (int ni = 0; ni < 8; ni++)
#pragma unroll
            for (int q = 0; q < 4; q++) acc[mi][ni][q] = 0.0f;

    // per-thread source/destination for this thread's 8 cp.async ops
    const int ld_row = tid >> 3;                 // 0..31
    const int ld_c   = (tid & 7) << 3;           // halves

    // full-stage loader (prologue only)
    auto load_stage = [&](int kc, int s) {
        char* As = smem + s * STG_BYTES;
        char* Bs = As + A_BYTES;
#pragma unroll
        for (int i = 0; i < 4; i++) {
            int row = ld_row + i * 32;
            cp_async16(As + row * ROWB + ld_c * 2,
                       Ag + (size_t)(bm + row) * K_ACT + kc * KC + ld_c);
            cp_async16(Bs + row * ROWB + ld_c * 2,
                       Bg + (size_t)(bn + row) * K_ACT + kc * KC + ld_c);
        }
    };

    // ldmatrix per-lane row addressing (byte offsets)
    const uint32_t smem_b = smem_u32(smem);
    const int a_row  = wm * 32 + (lane & 7) + (lane & 8);
    const int a_koff = (lane >> 4) << 3;            // halves
    const int b_row  = wn * 64 + (lane & 7) + ((lane >> 4) << 3);
    const int b_koff = (lane & 8);                  // halves

    // prologue: stages 0 and 1 in flight
    load_stage(0, 0);
    asm volatile("cp.async.commit_group;" ::: "memory");
    load_stage(1, 1);
    asm volatile("cp.async.commit_group;" ::: "memory");

    // ---- distributed zeroing (prologue; fire-and-forget .cs stores) ----
    // Zero inactive dense rows of this tile's interval, this CTA's 128-col
    // stripe. Stores drain behind the whole mainloop; .cs avoids L2 pollution.
    for (int r = zlo + tid; r < zhi; r += 256) {
        int lo = bm, hi = bm + MT;
        while (lo < hi) {
            int mid = (lo + hi) >> 1;
            if (__ldg(indices + mid) < r) lo = mid + 1; else hi = mid;
        }
        if (lo < bm + MT && __ldg(indices + lo) == r) continue;   // active row
        float* p = out + (size_t)r * N_TOK + bn;
#pragma unroll
        for (int i = 0; i < NT / 4; i++)
            stg_cs_v4(p + i * 4, 0.f, 0.f, 0.f, 0.f);
    }

    int s_cur = 0, s_nxt = 2;
    for (int kc = 0; kc < KITERS; kc++) {
        asm volatile("cp.async.wait_group 1;" ::: "memory");   // stage kc ready
        __syncthreads();   // all warps done with compute(kc-1) -> slot s_nxt free

        const bool do_load = (kc + 2 < KITERS);
        char* Asn = smem + s_nxt * STG_BYTES;
        char* Bsn = Asn + A_BYTES;
        const __half* Agn = Ag + (size_t)bm * K_ACT + (kc + 2) * KC;
        const __half* Bgn = Bg + (size_t)bn * K_ACT + (kc + 2) * KC;

        const uint32_t As = smem_b + s_cur * STG_BYTES;
        const uint32_t Bs = As + A_BYTES;
        const uint32_t aAddr = As + a_row * ROWB + a_koff * 2;
        const uint32_t bAddr = Bs + b_row * ROWB + b_koff * 2;

#pragma unroll
        for (int ks = 0; ks < 4; ks++) {
            const int k0b = ks * 32;                // k16 * 2 bytes
            uint32_t aa[2][4];
#pragma unroll
            for (int mi = 0; mi < 2; mi++)
                ldsm_x4(aa[mi], aAddr + mi * 16 * ROWB + k0b);
            uint32_t bb[4][4];
#pragma unroll
            for (int pr = 0; pr < 4; pr++)
                ldsm_x4(bb[pr], bAddr + pr * 16 * ROWB + k0b);
            // 2 of this thread's 8 next-stage cp.async ops while LDSMs fly
            if (do_load) {
                int row = ld_row + ks * 32;
                cp_async16(Asn + row * ROWB + ld_c * 2,
                           Agn + (size_t)row * K_ACT + ld_c);
                cp_async16(Bsn + row * ROWB + ld_c * 2,
                           Bgn + (size_t)row * K_ACT + ld_c);
            }
#pragma unroll
            for (int mi = 0; mi < 2; mi++)
#pragma unroll
                for (int ni = 0; ni < 8; ni++)
                    mma_f16(acc[mi][ni], aa[mi],
                            bb[ni >> 1][(ni & 1) * 2],
                            bb[ni >> 1][(ni & 1) * 2 + 1]);
        }
        asm volatile("cp.async.commit_group;" ::: "memory");   // stage kc+2 group
        s_cur = (s_cur + 1 == STAGES) ? 0 : s_cur + 1;
        s_nxt = (s_nxt + 1 == STAGES) ? 0 : s_nxt + 1;
    }

    // ---- epilogue: scatter GEMM rows via prefetched indices (.cs stores) ----
    const int orow[2][2] = {{o_r0, o_r8}, {o_r16, o_r24}};
#pragma unroll
    for (int mi = 0; mi < 2; mi++) {
        float* d0 = out + (size_t)orow[mi][0] * N_TOK + bn + wn * 64 + 2 * (lane & 3);
        float* d1 = out + (size_t)orow[mi][1] * N_TOK + bn + wn * 64 + 2 * (lane & 3);
#pragma unroll
        for (int ni = 0; ni < 8; ni++) {
            stg_cs_v2(d0 + ni * 8, acc[mi][ni][0], acc[mi][ni][1]);
            stg_cs_v2(d1 + ni * 8, acc[mi][ni][2], acc[mi][ni][3]);
        }
    }
}

// ===========================================================================
// Host launcher
// ===========================================================================
extern "C" void kernel_launch(void* const* d_in, const int* in_sizes, int n_in,
                              void* d_out, int out_size) {
    const float* input    = (const float*)d_in[0];
    const int*   idx      = (const int*)  d_in[1];
    const float* weight   = (const float*)d_in[2];
    const int*   indices  = (const int*)  d_in[3];
    const int*   metadata = (const int*)  d_in[4];
    if (in_sizes[1] == O_DIM && in_sizes[3] == K_ACT) {
        const int* t = idx; idx = indices; indices = t;
    }
    float* out = (float*)d_out;

    cudaFuncSetAttribute(gemm_mma_kernel,
                         cudaFuncAttributeMaxDynamicSharedMemorySize, SMEM_DYN);

    // 1) fused prep: gather+convert weight, convert activations
    prep_kernel<<<PREP_GRID, 256>>>(weight, idx, metadata, (const float4*)input);
    // 2) tensor-core GEMM + scatter + prologue zeroing
    dim3 grid(N_TOK / NT, O_DIM / MT);   // 32 x 32
    gemm_mma_kernel<<<grid, 256, SMEM_DYN>>>(indices, out);
}